// round 15
// baseline (speedup 1.0000x reference)
#include <cuda_runtime.h>
#include <cuda_fp16.h>
#include <cstdint>

#define BSZ 16
#define TT  1024
#define EMB 768
#define HID 1024
#define MROWS (BSZ*TT)

// ================= scratch =================
__device__ __align__(128) __half g_ABh [(size_t)2*MROWS*2*EMB];
__device__ __align__(128) __half g_W1Th[(size_t)HID*2*EMB];
__device__ __align__(128) __half g_W2Th[(size_t)HID*2*HID];
__device__ __align__(128) __half g_Hh  [(size_t)2*MROWS*2*HID];
__device__ __align__(128) __half g_Fh  [(size_t)2*MROWS*2*HID];
__device__ __align__(128) float  g_E   [(size_t)BSZ*TT*TT];
__device__ __align__(128) __half g_Pall[(size_t)2*BSZ*TT*TT];   // [P2 | P]
__device__ float g_rmax[MROWS], g_rsum[MROWS], g_cmax[MROWS], g_csum[MROWS];
__device__ float g_rpm[16*MROWS], g_rps[16*MROWS];  // row partials (16 n-blocks)
__device__ float g_cpm[8*MROWS],  g_cps[8*MROWS];   // col partials (8 m-blocks)

// ================= helpers =================
__device__ __forceinline__ uint32_t smem_u32(const void* p) {
    uint32_t a;
    asm("{ .reg .u64 t; cvta.to.shared.u64 t, %1; cvt.u32.u64 %0, t; }" : "=r"(a) : "l"(p));
    return a;
}
__device__ __forceinline__ void mma_f16(float* d, const uint32_t* a, const uint32_t* b) {
    asm volatile("mma.sync.aligned.m16n8k16.row.col.f32.f16.f16.f32 "
        "{%0,%1,%2,%3}, {%4,%5,%6,%7}, {%8,%9}, {%0,%1,%2,%3};"
        : "+f"(d[0]), "+f"(d[1]), "+f"(d[2]), "+f"(d[3])
        : "r"(a[0]), "r"(a[1]), "r"(a[2]), "r"(a[3]), "r"(b[0]), "r"(b[1]));
}
__device__ __forceinline__ void ldsm(uint32_t* r, uint32_t a) {
    asm volatile("ldmatrix.sync.aligned.m8n8.x4.shared.b16 {%0,%1,%2,%3}, [%4];"
        : "=r"(r[0]), "=r"(r[1]), "=r"(r[2]), "=r"(r[3]) : "r"(a));
}
__device__ __forceinline__ void ldsmT(uint32_t* r, uint32_t a) {
    asm volatile("ldmatrix.sync.aligned.m8n8.x4.trans.shared.b16 {%0,%1,%2,%3}, [%4];"
        : "=r"(r[0]), "=r"(r[1]), "=r"(r[2]), "=r"(r[3]) : "r"(a));
}
__device__ __forceinline__ void cp16(uint32_t d, const void* s) {
    asm volatile("cp.async.cg.shared.global [%0], [%1], 16;" :: "r"(d), "l"(s) : "memory");
}
__device__ __forceinline__ void split_h(float v, __half& hi, __half& lo) {
    hi = __float2half_rn(v);
    lo = __float2half_rn(v - __half2float(hi));
}
__device__ __forceinline__ void sm_merge(float& m, float& s, float om, float os) {
    float M = fmaxf(m, om);
    s = s * __expf(m - M) + os * __expf(om - M);
    m = M;
}

// ================= fp16 mma GEMM =================
// SPLIT3: C = [act](Ah*Bh^T + Ah*Bl^T + Al*Bh^T + bias); lo at col offset loK.
//   Smem stage = rows [Ahi(128)|Alo(128)|Bhi(BNV)|Blo(BNV)] x 80B.
// !SPLIT3: C = A(M,K)*B(K,N), B row-major via ldmatrix.trans (beta/alpha).
#define BM 128
#define BKH 32
#define NTHR 256
#define SROW 80
#define SROWT 272
#define STGP 18944u
#define BT_OFF  10240u
#define SMEMP (2*18944)

template<int BNV, bool SPLIT3>
__device__ __forceinline__ void cp_stage32(uint32_t st,
    const __half* __restrict__ ga, int lda,
    const __half* __restrict__ gb, int ldb, int loK, int tid)
{
    if (SPLIT3) {
        constexpr int CHUNKS = (256 + 2 * BNV) * 4;
#pragma unroll
        for (int i = 0; i < CHUNKS / NTHR; ++i) {
            int u = tid + i * NTHR;
            int ru = u >> 2, c = u & 3;
            const __half* src;
            if (ru < 256) {
                src = ga + ((ru >= 128) ? loK : 0) + (size_t)(ru & 127) * lda + c * 8;
            } else {
                int rb = ru - 256;
                bool lo = rb >= BNV;
                src = gb + (lo ? loK : 0) + (size_t)(lo ? rb - BNV : rb) * ldb + c * 8;
            }
            cp16(st + (uint32_t)(ru * SROW + c * 16), src);
        }
    } else {
#pragma unroll
        for (int i = 0; i < 2; ++i) {
            int u = tid + i * NTHR, r = u >> 2, c = u & 3;
            cp16(st + (uint32_t)(r * SROW + c * 16), ga + (size_t)r * lda + c * 8);
        }
#pragma unroll
        for (int i = 0; i < 2; ++i) {
            int u = tid + i * NTHR, r = u >> 4, c = u & 15;
            cp16(st + BT_OFF + (uint32_t)(r * SROWT + c * 16), gb + (size_t)r * ldb + c * 8);
        }
    }
}

template<int BNV, bool SPLIT3, bool BIASRELU, bool HALFSPLITOUT, bool SWAPOUT, bool STATS>
__global__ void __launch_bounds__(NTHR, 2)
gemm_h(const __half* __restrict__ Aop, int lda, unsigned long long sA,
       const __half* __restrict__ Bop, int ldb, unsigned long long sB,
       const float* __restrict__ bias,
       void* __restrict__ Cv, int ldc, unsigned long long sC,
       int N, int K, int loK,
       float* __restrict__ rpm, float* __restrict__ rps,
       float* __restrict__ cpm, float* __restrict__ cps)
{
    extern __shared__ __align__(128) __half smh[];
    uint32_t sbase = smem_u32(smh);
    constexpr int NI = BNV / 32;                       // 8-col MMA blocks / warp
    constexpr int PN = BNV / 64;                       // ldsm x4 groups / warp
    constexpr uint32_t BHI_OFF = 256u * SROW;
    constexpr uint32_t BLO_OFF = (uint32_t)(256 + BNV) * SROW;
    constexpr uint32_t ALO_OFF = 128u * SROW;
    constexpr uint32_t STG = SPLIT3 ? (uint32_t)((256 + 2 * BNV) * SROW) : STGP;
    const int tid = threadIdx.x, lane = tid & 31, wid = tid >> 5;
    const int wm = wid >> 2, wn = wid & 3, gr = lane >> 2, tc = lane & 3;
    const int m0 = blockIdx.y * BM, n0 = blockIdx.x * BNV;
    const int z  = blockIdx.z;

    const __half* Abase = Aop + (size_t)z * sA + (size_t)m0 * lda;
    const __half* Bbase = SPLIT3
        ? (Bop + (size_t)z * sB + (size_t)n0 * ldb)
        : (Bop + (size_t)z * sB + n0);
    const int NT = K / BKH;

    const int lg = lane >> 3, r8 = lane & 7;
    uint32_t aOff[4], bOff[PN];
#pragma unroll
    for (int mi = 0; mi < 4; ++mi)
        aOff[mi] = (uint32_t)((wm * 64 + mi * 16 + (lg & 1) * 8 + r8) * SROW
                              + (lg >> 1) * 16);
#pragma unroll
    for (int pn = 0; pn < PN; ++pn) {
        if (SPLIT3)
            bOff[pn] = (uint32_t)((wn * (BNV/4) + pn * 16 + (lg >> 1) * 8 + r8) * SROW
                                  + (lg & 1) * 16);
        else
            bOff[pn] = (uint32_t)(((lg & 1) * 8 + r8) * SROWT
                                  + (wn * (BNV/4) + pn * 16 + (lg >> 1) * 8) * 2);
    }

    float acc[4][NI][4];
#pragma unroll
    for (int i = 0; i < 4; ++i)
#pragma unroll
        for (int j = 0; j < NI; ++j)
#pragma unroll
            for (int k = 0; k < 4; ++k) acc[i][j][k] = 0.f;

    cp_stage32<BNV, SPLIT3>(sbase, Abase, lda, Bbase, ldb, loK, tid);
    asm volatile("cp.async.commit_group;" ::: "memory");

#pragma unroll 1
    for (int kt = 0; kt < NT; ++kt) {
        asm volatile("cp.async.wait_group 0;" ::: "memory");
        __syncthreads();
        if (kt + 1 < NT) {
            uint32_t st = sbase + (uint32_t)((kt + 1) & 1) * STG;
            const __half* ga = Abase + (kt + 1) * BKH;
            const __half* gb = SPLIT3 ? (Bbase + (kt + 1) * BKH)
                                      : (Bbase + (size_t)(kt + 1) * BKH * ldb);
            cp_stage32<BNV, SPLIT3>(st, ga, lda, gb, ldb, loK, tid);
            asm volatile("cp.async.commit_group;" ::: "memory");
        }
        uint32_t st = sbase + (uint32_t)(kt & 1) * STG;
#pragma unroll
        for (int ks = 0; ks < 2; ++ks) {
            if (SPLIT3) {
                const uint32_t kb = (uint32_t)(ks * 32);
                uint32_t bh[NI][2], bl[NI][2];
#pragma unroll
                for (int pn = 0; pn < PN; ++pn) {
                    uint32_t t[4];
                    ldsm(t, st + BHI_OFF + bOff[pn] + kb);
                    bh[2*pn][0]=t[0]; bh[2*pn][1]=t[1]; bh[2*pn+1][0]=t[2]; bh[2*pn+1][1]=t[3];
                    ldsm(t, st + BLO_OFF + bOff[pn] + kb);
                    bl[2*pn][0]=t[0]; bl[2*pn][1]=t[1]; bl[2*pn+1][0]=t[2]; bl[2*pn+1][1]=t[3];
                }
#pragma unroll
                for (int mi = 0; mi < 4; ++mi) {
                    uint32_t ah[4], al[4];
                    ldsm(ah, st + aOff[mi] + kb);
                    ldsm(al, st + ALO_OFF + aOff[mi] + kb);
#pragma unroll
                    for (int ni = 0; ni < NI; ++ni) mma_f16(acc[mi][ni], ah, bh[ni]);
#pragma unroll
                    for (int ni = 0; ni < NI; ++ni) mma_f16(acc[mi][ni], al, bh[ni]);
#pragma unroll
                    for (int ni = 0; ni < NI; ++ni) mma_f16(acc[mi][ni], ah, bl[ni]);
                }
            } else {
                const uint32_t kbA = (uint32_t)(ks * 32);
                const uint32_t kbB = (uint32_t)(ks * 16 * SROWT);
                uint32_t bf[NI][2];
#pragma unroll
                for (int pn = 0; pn < PN; ++pn) {
                    uint32_t t[4];
                    ldsmT(t, st + BT_OFF + bOff[pn] + kbB);
                    bf[2*pn][0]=t[0]; bf[2*pn][1]=t[1]; bf[2*pn+1][0]=t[2]; bf[2*pn+1][1]=t[3];
                }
#pragma unroll
                for (int mi = 0; mi < 4; ++mi) {
                    uint32_t af[4];
                    ldsm(af, st + aOff[mi] + kbA);
#pragma unroll
                    for (int ni = 0; ni < NI; ++ni) mma_f16(acc[mi][ni], af, bf[ni]);
                }
            }
        }
    }

    // ---- store ----
    int ob = SWAPOUT ? ((z < BSZ) ? (BSZ + z) : (z - BSZ)) : z;
#pragma unroll
    for (int ni = 0; ni < NI; ++ni) {
        int col = n0 + wn * (BNV/4) + ni * 8 + 2 * tc;
        float b0 = 0.f, b1 = 0.f;
        if (BIASRELU) { b0 = __ldg(bias + col); b1 = __ldg(bias + col + 1); }
#pragma unroll
        for (int mi = 0; mi < 4; ++mi) {
            int row0 = m0 + wm * 64 + mi * 16 + gr;
            float v00 = acc[mi][ni][0], v01 = acc[mi][ni][1];
            float v10 = acc[mi][ni][2], v11 = acc[mi][ni][3];
            if (BIASRELU) {
                v00 = fmaxf(v00 + b0, 0.f); v01 = fmaxf(v01 + b1, 0.f);
                v10 = fmaxf(v10 + b0, 0.f); v11 = fmaxf(v11 + b1, 0.f);
                acc[mi][ni][0]=v00; acc[mi][ni][1]=v01; acc[mi][ni][2]=v10; acc[mi][ni][3]=v11;
            }
            if (HALFSPLITOUT) {
                __half* C = (__half*)Cv + (size_t)ob * sC;
                __half h00,l00,h01,l01,h10,l10,h11,l11;
                split_h(v00,h00,l00); split_h(v01,h01,l01);
                split_h(v10,h10,l10); split_h(v11,h11,l11);
                __half* p0 = C + (size_t)row0 * ldc + col;
                __half* p1 = C + (size_t)(row0 + 8) * ldc + col;
                *(__half2*)p0       = __halves2half2(h00, h01);
                *(__half2*)(p0 + N) = __halves2half2(l00, l01);
                *(__half2*)p1       = __halves2half2(h10, h11);
                *(__half2*)(p1 + N) = __halves2half2(l10, l11);
            } else {
                float* C = (float*)Cv + (size_t)ob * sC;
                *(float2*)(C + (size_t)row0 * ldc + col)       = make_float2(v00, v01);
                *(float2*)(C + (size_t)(row0 + 8) * ldc + col) = make_float2(v10, v11);
            }
        }
    }

    // ---- fused softmax partial stats (e-GEMM only) ----
    if (STATS) {
        __syncthreads();
        float2* smR = (float2*)smh;                 // [128][4]
        float2* smC = ((float2*)smh) + 512;         // [BNV][2]
#pragma unroll
        for (int mi = 0; mi < 4; ++mi)
#pragma unroll
            for (int h = 0; h < 2; ++h) {
                float m = -1e30f;
#pragma unroll
                for (int ni = 0; ni < NI; ++ni)
                    m = fmaxf(m, fmaxf(acc[mi][ni][2*h], acc[mi][ni][2*h+1]));
                float s = 0.f;
#pragma unroll
                for (int ni = 0; ni < NI; ++ni)
                    s += __expf(acc[mi][ni][2*h] - m) + __expf(acc[mi][ni][2*h+1] - m);
#pragma unroll
                for (int o = 1; o <= 2; o <<= 1)
                    sm_merge(m, s, __shfl_xor_sync(~0u, m, o), __shfl_xor_sync(~0u, s, o));
                if (tc == 0)
                    smR[(wm*64 + mi*16 + h*8 + gr) * 4 + wn] = make_float2(m, s);
            }
#pragma unroll
        for (int ni = 0; ni < NI; ++ni)
#pragma unroll
            for (int j = 0; j < 2; ++j) {
                float m = -1e30f;
#pragma unroll
                for (int mi = 0; mi < 4; ++mi)
                    m = fmaxf(m, fmaxf(acc[mi][ni][j], acc[mi][ni][j+2]));
                float s = 0.f;
#pragma unroll
                for (int mi = 0; mi < 4; ++mi)
                    s += __expf(acc[mi][ni][j] - m) + __expf(acc[mi][ni][j+2] - m);
#pragma unroll
                for (int o = 4; o <= 16; o <<= 1)
                    sm_merge(m, s, __shfl_xor_sync(~0u, m, o), __shfl_xor_sync(~0u, s, o));
                if (gr == 0)
                    smC[(wn*(BNV/4) + ni*8 + 2*tc + j) * 2 + wm] = make_float2(m, s);
            }
        __syncthreads();
        if (tid < 128) {
            float2 p = smR[tid * 4];
            float m = p.x, s = p.y;
#pragma unroll
            for (int w = 1; w < 4; ++w) {
                float2 q = smR[tid * 4 + w];
                sm_merge(m, s, q.x, q.y);
            }
            size_t idx = (size_t)blockIdx.x * MROWS + (size_t)z * TT + m0 + tid;
            rpm[idx] = m; rps[idx] = s;
        } else if (tid < 128 + BNV) {
            int cl = tid - 128;
            float2 p = smC[cl * 2];
            float m = p.x, s = p.y;
            float2 q = smC[cl * 2 + 1];
            sm_merge(m, s, q.x, q.y);
            size_t idx = (size_t)blockIdx.y * MROWS + (size_t)z * TT + n0 + cl;
            cpm[idx] = m; cps[idx] = s;
        }
    }
}

// ================= prep =================
#define NSPA ((MROWS*EMB)/1024)
#define NW1  ((EMB/32)*(HID/32))
#define NW2  ((HID/32)*(HID/32))
#define PREP_BLOCKS (2*NSPA + NW1 + NW2)

__global__ void __launch_bounds__(256)
prep_kernel(const float* __restrict__ A, const float* __restrict__ Bn,
            const float* __restrict__ W1, const float* __restrict__ W2,
            __half* __restrict__ ABh, __half* __restrict__ W1Th,
            __half* __restrict__ W2Th)
{
    __shared__ float tile[32][33];
    int id = blockIdx.x, tid = threadIdx.x;
    if (id < 2 * NSPA) {
        bool isA = id < NSPA;
        const float4* src = (const float4*)(isA ? A : Bn);
        size_t i = (size_t)(id - (isA ? 0 : NSPA)) * 256 + tid;
        float4 v = src[i];
        size_t row = i / (EMB/4) + (isA ? 0 : (size_t)MROWS);
        size_t c = (i % (EMB/4)) * 4;
        __half h0,l0,h1,l1,h2,l2,h3,l3;
        split_h(v.x,h0,l0); split_h(v.y,h1,l1); split_h(v.z,h2,l2); split_h(v.w,h3,l3);
        __half* dst = ABh + row * (2*EMB) + c;
        *(__half2*)dst         = __halves2half2(h0,h1);
        *(__half2*)(dst+2)     = __halves2half2(h2,h3);
        *(__half2*)(dst+EMB)   = __halves2half2(l0,l1);
        *(__half2*)(dst+EMB+2) = __halves2half2(l2,l3);
        return;
    }
    id -= 2 * NSPA;
    int tx = tid & 31, ty = tid >> 5;
    bool isW1 = id < NW1;
    int id2 = isW1 ? id : id - NW1;
    int R = isW1 ? EMB : HID;
    const float* W = isW1 ? W1 : W2;
    __half* WT = isW1 ? W1Th : W2Th;
    int rt = R / 32;
    int r0 = (id2 % rt) * 32, c0 = (id2 / rt) * 32;
#pragma unroll
    for (int k = 0; k < 4; ++k)
        tile[k*8+ty][tx] = W[(size_t)(r0 + k*8 + ty) * HID + c0 + tx];
    __syncthreads();
#pragma unroll
    for (int k = 0; k < 4; ++k) {
        int c = c0 + k*8 + ty;
        float v = tile[tx][k*8+ty];
        __half h, l; split_h(v, h, l);
        WT[(size_t)c * (2*R) + r0 + tx]     = h;
        WT[(size_t)c * (2*R) + R + r0 + tx] = l;
    }
}

// ================= combine partials =================
__global__ void __launch_bounds__(256)
combine_kernel(const float* __restrict__ rpm, const float* __restrict__ rps,
               const float* __restrict__ cpm, const float* __restrict__ cps,
               float* __restrict__ rmax, float* __restrict__ rsum,
               float* __restrict__ cmax, float* __restrict__ csum)
{
    int g = blockIdx.x * 256 + threadIdx.x;
    if (g < MROWS) {
        float m = rpm[g], s = rps[g];
#pragma unroll
        for (int k = 1; k < 16; ++k)
            sm_merge(m, s, rpm[(size_t)k * MROWS + g], rps[(size_t)k * MROWS + g]);
        rmax[g] = m; rsum[g] = s;
    } else {
        int id = g - MROWS;
        float m = cpm[id], s = cps[id];
#pragma unroll
        for (int k = 1; k < 8; ++k)
            sm_merge(m, s, cpm[(size_t)k * MROWS + id], cps[(size_t)k * MROWS + id]);
        cmax[id] = m; csum[id] = s;
    }
}

// ================= normalize =================
__global__ void __launch_bounds__(256)
normexp_kernel(const float* __restrict__ E, __half* __restrict__ Pall,
               const float* __restrict__ rmax, const float* __restrict__ rsum,
               const float* __restrict__ cmax, const float* __restrict__ csum)
{
    __shared__ float tile[32][33];
    int b = blockIdx.z, a0 = blockIdx.y * 32, c0 = blockIdx.x * 32;
    int tx = threadIdx.x, ty = threadIdx.y;
    const float* Eb = E + (size_t)b * TT * TT;
    __half* P2b = Pall + (size_t)b * TT * TT;
    __half* Pb  = Pall + (size_t)(BSZ + b) * TT * TT;
#pragma unroll
    for (int k = 0; k < 4; ++k) {
        int a = a0 + k*8 + ty;
        float v = Eb[(size_t)a * TT + c0 + tx];
        tile[k*8+ty][tx] = v;
        int grr = b * TT + a;
        Pb[(size_t)a * TT + c0 + tx] =
            __float2half_rn(__expf(v - rmax[grr]) * __frcp_rn(rsum[grr]));
    }
    __syncthreads();
#pragma unroll
    for (int k = 0; k < 4; ++k) {
        int c = c0 + k*8 + ty;
        float v = tile[tx][k*8+ty];
        int gc = b * TT + c;
        P2b[(size_t)c * TT + a0 + tx] =
            __float2half_rn(__expf(v - cmax[gc]) * __frcp_rn(csum[gc]));
    }
}

// ================= launch =================
extern "C" void kernel_launch(void* const* d_in, const int* in_sizes, int n_in,
                              void* d_out, int out_size)
{
    const float* Ain = (const float*)d_in[0];
    const float* Bin = (const float*)d_in[1];
    const float* W1  = (const float*)d_in[2];
    const float* b1  = (const float*)d_in[3];
    const float* W2  = (const float*)d_in[4];
    const float* b2  = (const float*)d_in[5];
    float* outp = (float*)d_out;

    __half *ABh, *W1Th, *W2Th, *Hh, *Fh, *Pall;
    float *E, *rm, *rs, *cm, *cs, *rpm, *rps, *cpm, *cps;
    cudaGetSymbolAddress((void**)&ABh,  g_ABh);
    cudaGetSymbolAddress((void**)&W1Th, g_W1Th);
    cudaGetSymbolAddress((void**)&W2Th, g_W2Th);
    cudaGetSymbolAddress((void**)&Hh,   g_Hh);
    cudaGetSymbolAddress((void**)&Fh,   g_Fh);
    cudaGetSymbolAddress((void**)&E,    g_E);
    cudaGetSymbolAddress((void**)&Pall, g_Pall);
    cudaGetSymbolAddress((void**)&rm,   g_rmax);
    cudaGetSymbolAddress((void**)&rs,   g_rsum);
    cudaGetSymbolAddress((void**)&cm,   g_cmax);
    cudaGetSymbolAddress((void**)&cs,   g_csum);
    cudaGetSymbolAddress((void**)&rpm,  g_rpm);
    cudaGetSymbolAddress((void**)&rps,  g_rps);
    cudaGetSymbolAddress((void**)&cpm,  g_cpm);
    cudaGetSymbolAddress((void**)&cps,  g_cps);

    constexpr int SMEM3_128 = 2 * (256 + 256) * SROW;   // 81920
    constexpr int SMEM3_64  = 2 * (256 + 128) * SROW;   // 61440

    cudaFuncSetAttribute(gemm_h<128, true,  true,  true,  false, false>, cudaFuncAttributeMaxDynamicSharedMemorySize, SMEM3_128);
    cudaFuncSetAttribute(gemm_h<64,  true,  false, false, false, true >, cudaFuncAttributeMaxDynamicSharedMemorySize, SMEM3_64);
    cudaFuncSetAttribute(gemm_h<128, false, false, false, true,  false>, cudaFuncAttributeMaxDynamicSharedMemorySize, SMEMP);

    // 1) prep
    prep_kernel<<<PREP_BLOCKS, 256>>>(Ain, Bin, W1, W2, ABh, W1Th, W2Th);

    // 2) MLP layer 1
    gemm_h<128, true, true, true, false, false><<<dim3(HID/128, 2*MROWS/BM, 1), NTHR, SMEM3_128>>>(
        ABh, 2*EMB, 0, W1Th, 2*EMB, 0, b1, Hh, 2*HID, 0, HID, EMB, EMB,
        nullptr, nullptr, nullptr, nullptr);

    // 3) MLP layer 2
    gemm_h<128, true, true, true, false, false><<<dim3(HID/128, 2*MROWS/BM, 1), NTHR, SMEM3_128>>>(
        Hh, 2*HID, 0, W2Th, 2*HID, 0, b2, Fh, 2*HID, 0, HID, HID, HID,
        nullptr, nullptr, nullptr, nullptr);

    // 4) e = f_A @ f_B^T with fused softmax partial stats; BN=64 for tail
    gemm_h<64, true, false, false, false, true><<<dim3(TT/64, TT/BM, BSZ), NTHR, SMEM3_64>>>(
        Fh, 2*HID, (unsigned long long)TT*2*HID,
        Fh + (size_t)MROWS*2*HID, 2*HID, (unsigned long long)TT*2*HID,
        nullptr, E, TT, (unsigned long long)TT*TT, TT, HID, HID,
        rpm, rps, cpm, cps);

    // 5) combine partials
    combine_kernel<<<2*MROWS/256, 256>>>(rpm, rps, cpm, cps, rm, rs, cm, cs);

    // 6) normalize -> Pall = [P2 | P]
    normexp_kernel<<<dim3(TT/32, TT/32, BSZ), dim3(32, 8)>>>(E, Pall, rm, rs, cm, cs);

    // 7) alpha (z 0..15: P2 @ A) + beta (z 16..31: P @ B)
    gemm_h<128, false, false, false, true, false><<<dim3(EMB/128, TT/BM, 2*BSZ), NTHR, SMEMP>>>(
        Pall, TT, (unsigned long long)TT*TT,
        ABh, 2*EMB, (unsigned long long)TT*2*EMB,
        nullptr, outp, EMB, (unsigned long long)TT*EMB, EMB, TT, 0,
        nullptr, nullptr, nullptr, nullptr);
}

// round 16
// speedup vs baseline: 1.0327x; 1.0327x over previous
#include <cuda_runtime.h>
#include <cuda_fp16.h>
#include <cstdint>

#define BSZ 16
#define TT  1024
#define EMB 768
#define HID 1024
#define MROWS (BSZ*TT)

// ================= scratch =================
__device__ __align__(128) __half g_ABh [(size_t)2*MROWS*2*EMB];
__device__ __align__(128) __half g_W1Th[(size_t)HID*2*EMB];
__device__ __align__(128) __half g_W2Th[(size_t)HID*2*HID];
__device__ __align__(128) __half g_Hh  [(size_t)2*MROWS*2*HID];
__device__ __align__(128) __half g_Fh  [(size_t)2*MROWS*2*HID];
__device__ __align__(128) float  g_E   [(size_t)BSZ*TT*TT];
__device__ __align__(128) __half g_Pall[(size_t)2*BSZ*TT*TT];   // [P2 | P]
__device__ float g_rmax[MROWS], g_rsum[MROWS], g_cmax[MROWS], g_csum[MROWS];
__device__ float g_rpm[8*MROWS], g_rps[8*MROWS];   // row partials (per n-block)
__device__ float g_cpm[8*MROWS], g_cps[8*MROWS];   // col partials (per m-block)

// ================= helpers =================
__device__ __forceinline__ uint32_t smem_u32(const void* p) {
    uint32_t a;
    asm("{ .reg .u64 t; cvta.to.shared.u64 t, %1; cvt.u32.u64 %0, t; }" : "=r"(a) : "l"(p));
    return a;
}
__device__ __forceinline__ void mma_f16(float* d, const uint32_t* a, const uint32_t* b) {
    asm volatile("mma.sync.aligned.m16n8k16.row.col.f32.f16.f16.f32 "
        "{%0,%1,%2,%3}, {%4,%5,%6,%7}, {%8,%9}, {%0,%1,%2,%3};"
        : "+f"(d[0]), "+f"(d[1]), "+f"(d[2]), "+f"(d[3])
        : "r"(a[0]), "r"(a[1]), "r"(a[2]), "r"(a[3]), "r"(b[0]), "r"(b[1]));
}
__device__ __forceinline__ void ldsm(uint32_t* r, uint32_t a) {
    asm volatile("ldmatrix.sync.aligned.m8n8.x4.shared.b16 {%0,%1,%2,%3}, [%4];"
        : "=r"(r[0]), "=r"(r[1]), "=r"(r[2]), "=r"(r[3]) : "r"(a));
}
__device__ __forceinline__ void ldsmT(uint32_t* r, uint32_t a) {
    asm volatile("ldmatrix.sync.aligned.m8n8.x4.trans.shared.b16 {%0,%1,%2,%3}, [%4];"
        : "=r"(r[0]), "=r"(r[1]), "=r"(r[2]), "=r"(r[3]) : "r"(a));
}
__device__ __forceinline__ void cp16(uint32_t d, const void* s) {
    asm volatile("cp.async.cg.shared.global [%0], [%1], 16;" :: "r"(d), "l"(s) : "memory");
}
__device__ __forceinline__ void split_h(float v, __half& hi, __half& lo) {
    hi = __float2half_rn(v);
    lo = __float2half_rn(v - __half2float(hi));
}
__device__ __forceinline__ void sm_merge(float& m, float& s, float om, float os) {
    float M = fmaxf(m, om);
    s = s * __expf(m - M) + os * __expf(om - M);
    m = M;
}

// ================= fp16 mma GEMM (fused 3-term split) =================
#define BM 128
#define BN 128
#define BKH 32
#define NTHR 256
#define SROW 80
#define SROWT 272
#define STG3 40960u
#define STGP 18944u
#define ALO_OFF 10240u
#define BHI_OFF 20480u
#define BLO_OFF 30720u
#define BT_OFF  10240u
#define SMEM3 (2*40960)
#define SMEMP (2*18944)

template<bool SPLIT3>
__device__ __forceinline__ void cp_stage32(uint32_t st,
    const __half* __restrict__ ga, int lda,
    const __half* __restrict__ gb, int ldb, int loK, int tid)
{
    if (SPLIT3) {
#pragma unroll
        for (int i = 0; i < 8; ++i) {
            int u = tid + i * NTHR;
            int mat = u >> 9;
            int r = (u >> 2) & 127;
            int c = u & 3;
            const __half* src = ((mat < 2) ? ga : gb)
                              + ((mat & 1) ? loK : 0)
                              + (size_t)r * ((mat < 2) ? lda : ldb) + c * 8;
            cp16(st + (uint32_t)((mat * 128 + r) * SROW + c * 16), src);
        }
    } else {
#pragma unroll
        for (int i = 0; i < 2; ++i) {
            int u = tid + i * NTHR, r = u >> 2, c = u & 3;
            cp16(st + (uint32_t)(r * SROW + c * 16), ga + (size_t)r * lda + c * 8);
        }
#pragma unroll
        for (int i = 0; i < 2; ++i) {
            int u = tid + i * NTHR, r = u >> 4, c = u & 15;
            cp16(st + BT_OFF + (uint32_t)(r * SROWT + c * 16), gb + (size_t)r * ldb + c * 8);
        }
    }
}

template<bool SPLIT3, bool BIASRELU, bool HALFSPLITOUT, bool SWAPOUT, bool STATS>
__global__ void __launch_bounds__(NTHR, 2)
gemm_h(const __half* __restrict__ Aop, int lda, unsigned long long sA,
       const __half* __restrict__ Bop, int ldb, unsigned long long sB,
       const float* __restrict__ bias,
       void* __restrict__ Cv, int ldc, unsigned long long sC,
       int N, int K, int loK,
       float* __restrict__ rpm, float* __restrict__ rps,
       float* __restrict__ cpm, float* __restrict__ cps)
{
    extern __shared__ __align__(128) __half smh[];
    uint32_t sbase = smem_u32(smh);
    constexpr uint32_t STG = SPLIT3 ? STG3 : STGP;
    const int tid = threadIdx.x, lane = tid & 31, wid = tid >> 5;
    const int wm = wid >> 2, wn = wid & 3, gr = lane >> 2, tc = lane & 3;
    const int m0 = blockIdx.y * BM, n0 = blockIdx.x * BN;
    const int z  = blockIdx.z;

    const __half* Abase = Aop + (size_t)z * sA + (size_t)m0 * lda;
    const __half* Bbase = SPLIT3
        ? (Bop + (size_t)z * sB + (size_t)n0 * ldb)
        : (Bop + (size_t)z * sB + n0);
    const int NT = K / BKH;

    const int lg = lane >> 3, r8 = lane & 7;
    uint32_t aOff[4], bOff[2];
#pragma unroll
    for (int mi = 0; mi < 4; ++mi)
        aOff[mi] = (uint32_t)((wm * 64 + mi * 16 + (lg & 1) * 8 + r8) * SROW
                              + (lg >> 1) * 16);
#pragma unroll
    for (int pn = 0; pn < 2; ++pn) {
        if (SPLIT3)
            bOff[pn] = (uint32_t)((wn * 32 + pn * 16 + (lg >> 1) * 8 + r8) * SROW
                                  + (lg & 1) * 16);
        else
            bOff[pn] = (uint32_t)(((lg & 1) * 8 + r8) * SROWT
                                  + (wn * 32 + pn * 16 + (lg >> 1) * 8) * 2);
    }

    float acc[4][4][4];
#pragma unroll
    for (int i = 0; i < 4; ++i)
#pragma unroll
        for (int j = 0; j < 4; ++j)
#pragma unroll
            for (int k = 0; k < 4; ++k) acc[i][j][k] = 0.f;

    cp_stage32<SPLIT3>(sbase, Abase, lda, Bbase, ldb, loK, tid);
    asm volatile("cp.async.commit_group;" ::: "memory");

#pragma unroll 1
    for (int kt = 0; kt < NT; ++kt) {
        asm volatile("cp.async.wait_group 0;" ::: "memory");
        __syncthreads();
        if (kt + 1 < NT) {
            uint32_t st = sbase + (uint32_t)((kt + 1) & 1) * STG;
            const __half* ga = Abase + (kt + 1) * BKH;
            const __half* gb = SPLIT3 ? (Bbase + (kt + 1) * BKH)
                                      : (Bbase + (size_t)(kt + 1) * BKH * ldb);
            cp_stage32<SPLIT3>(st, ga, lda, gb, ldb, loK, tid);
            asm volatile("cp.async.commit_group;" ::: "memory");
        }
        uint32_t st = sbase + (uint32_t)(kt & 1) * STG;
#pragma unroll
        for (int ks = 0; ks < 2; ++ks) {
            if (SPLIT3) {
                const uint32_t kb = (uint32_t)(ks * 32);
                uint32_t bh[4][2], bl[4][2];
#pragma unroll
                for (int pn = 0; pn < 2; ++pn) {
                    uint32_t t[4];
                    ldsm(t, st + BHI_OFF + bOff[pn] + kb);
                    bh[2*pn][0]=t[0]; bh[2*pn][1]=t[1]; bh[2*pn+1][0]=t[2]; bh[2*pn+1][1]=t[3];
                    ldsm(t, st + BLO_OFF + bOff[pn] + kb);
                    bl[2*pn][0]=t[0]; bl[2*pn][1]=t[1]; bl[2*pn+1][0]=t[2]; bl[2*pn+1][1]=t[3];
                }
#pragma unroll
                for (int mi = 0; mi < 4; ++mi) {
                    uint32_t ah[4], al[4];
                    ldsm(ah, st + aOff[mi] + kb);
                    ldsm(al, st + ALO_OFF + aOff[mi] + kb);
#pragma unroll
                    for (int ni = 0; ni < 4; ++ni) mma_f16(acc[mi][ni], ah, bh[ni]);
#pragma unroll
                    for (int ni = 0; ni < 4; ++ni) mma_f16(acc[mi][ni], al, bh[ni]);
#pragma unroll
                    for (int ni = 0; ni < 4; ++ni) mma_f16(acc[mi][ni], ah, bl[ni]);
                }
            } else {
                const uint32_t kbA = (uint32_t)(ks * 32);
                const uint32_t kbB = (uint32_t)(ks * 16 * SROWT);
                uint32_t bf[4][2];
#pragma unroll
                for (int pn = 0; pn < 2; ++pn) {
                    uint32_t t[4];
                    ldsmT(t, st + BT_OFF + bOff[pn] + kbB);
                    bf[2*pn][0]=t[0]; bf[2*pn][1]=t[1]; bf[2*pn+1][0]=t[2]; bf[2*pn+1][1]=t[3];
                }
#pragma unroll
                for (int mi = 0; mi < 4; ++mi) {
                    uint32_t af[4];
                    ldsm(af, st + aOff[mi] + kbA);
#pragma unroll
                    for (int ni = 0; ni < 4; ++ni) mma_f16(acc[mi][ni], af, bf[ni]);
                }
            }
        }
    }

    // ---- store ----
    int ob = SWAPOUT ? ((z < BSZ) ? (BSZ + z) : (z - BSZ)) : z;
#pragma unroll
    for (int ni = 0; ni < 4; ++ni) {
        int col = n0 + wn * 32 + ni * 8 + 2 * tc;
        float b0 = 0.f, b1 = 0.f;
        if (BIASRELU) { b0 = __ldg(bias + col); b1 = __ldg(bias + col + 1); }
#pragma unroll
        for (int mi = 0; mi < 4; ++mi) {
            int row0 = m0 + wm * 64 + mi * 16 + gr;
            float v00 = acc[mi][ni][0], v01 = acc[mi][ni][1];
            float v10 = acc[mi][ni][2], v11 = acc[mi][ni][3];
            if (BIASRELU) {
                v00 = fmaxf(v00 + b0, 0.f); v01 = fmaxf(v01 + b1, 0.f);
                v10 = fmaxf(v10 + b0, 0.f); v11 = fmaxf(v11 + b1, 0.f);
                acc[mi][ni][0]=v00; acc[mi][ni][1]=v01; acc[mi][ni][2]=v10; acc[mi][ni][3]=v11;
            }
            if (HALFSPLITOUT) {
                __half* C = (__half*)Cv + (size_t)ob * sC;
                __half h00,l00,h01,l01,h10,l10,h11,l11;
                split_h(v00,h00,l00); split_h(v01,h01,l01);
                split_h(v10,h10,l10); split_h(v11,h11,l11);
                __half* p0 = C + (size_t)row0 * ldc + col;
                __half* p1 = C + (size_t)(row0 + 8) * ldc + col;
                *(__half2*)p0       = __halves2half2(h00, h01);
                *(__half2*)(p0 + N) = __halves2half2(l00, l01);
                *(__half2*)p1       = __halves2half2(h10, h11);
                *(__half2*)(p1 + N) = __halves2half2(l10, l11);
            } else {
                float* C = (float*)Cv + (size_t)ob * sC;
                *(float2*)(C + (size_t)row0 * ldc + col)       = make_float2(v00, v01);
                *(float2*)(C + (size_t)(row0 + 8) * ldc + col) = make_float2(v10, v11);
            }
        }
    }

    // ---- fused softmax partial stats (e-GEMM only) ----
    if (STATS) {
        __syncthreads();
        float2* smR = (float2*)smh;            // [128][4]
        float2* smC = ((float2*)smh) + 512;    // [128][2]
#pragma unroll
        for (int mi = 0; mi < 4; ++mi)
#pragma unroll
            for (int h = 0; h < 2; ++h) {
                float m = -1e30f;
#pragma unroll
                for (int ni = 0; ni < 4; ++ni)
                    m = fmaxf(m, fmaxf(acc[mi][ni][2*h], acc[mi][ni][2*h+1]));
                float s = 0.f;
#pragma unroll
                for (int ni = 0; ni < 4; ++ni)
                    s += __expf(acc[mi][ni][2*h] - m) + __expf(acc[mi][ni][2*h+1] - m);
#pragma unroll
                for (int o = 1; o <= 2; o <<= 1)
                    sm_merge(m, s, __shfl_xor_sync(~0u, m, o), __shfl_xor_sync(~0u, s, o));
                if (tc == 0)
                    smR[(wm*64 + mi*16 + h*8 + gr) * 4 + wn] = make_float2(m, s);
            }
#pragma unroll
        for (int ni = 0; ni < 4; ++ni)
#pragma unroll
            for (int j = 0; j < 2; ++j) {
                float m = -1e30f;
#pragma unroll
                for (int mi = 0; mi < 4; ++mi)
                    m = fmaxf(m, fmaxf(acc[mi][ni][j], acc[mi][ni][j+2]));
                float s = 0.f;
#pragma unroll
                for (int mi = 0; mi < 4; ++mi)
                    s += __expf(acc[mi][ni][j] - m) + __expf(acc[mi][ni][j+2] - m);
#pragma unroll
                for (int o = 4; o <= 16; o <<= 1)
                    sm_merge(m, s, __shfl_xor_sync(~0u, m, o), __shfl_xor_sync(~0u, s, o));
                if (gr == 0)
                    smC[(wn*32 + ni*8 + 2*tc + j) * 2 + wm] = make_float2(m, s);
            }
        __syncthreads();
        if (tid < 128) {
            float2 p = smR[tid * 4];
            float m = p.x, s = p.y;
#pragma unroll
            for (int w = 1; w < 4; ++w) {
                float2 q = smR[tid * 4 + w];
                sm_merge(m, s, q.x, q.y);
            }
            size_t idx = (size_t)blockIdx.x * MROWS + (size_t)z * TT + m0 + tid;
            rpm[idx] = m; rps[idx] = s;
        } else {
            int cl = tid - 128;
            float2 p = smC[cl * 2];
            float m = p.x, s = p.y;
            float2 q = smC[cl * 2 + 1];
            sm_merge(m, s, q.x, q.y);
            size_t idx = (size_t)blockIdx.y * MROWS + (size_t)z * TT + n0 + cl;
            cpm[idx] = m; cps[idx] = s;
        }
    }
}

// ================= prep (wide stores: 8 floats/thread) =================
#define NSPA ((MROWS*EMB)/2048)                 // 6144 blocks per tensor
#define NW1  ((EMB/32)*(HID/32))
#define NW2  ((HID/32)*(HID/32))
#define PREP_BLOCKS (2*NSPA + NW1 + NW2)

__global__ void __launch_bounds__(256)
prep_kernel(const float* __restrict__ A, const float* __restrict__ Bn,
            const float* __restrict__ W1, const float* __restrict__ W2,
            __half* __restrict__ ABh, __half* __restrict__ W1Th,
            __half* __restrict__ W2Th)
{
    __shared__ float tile[32][33];
    int id = blockIdx.x, tid = threadIdx.x;
    if (id < 2 * NSPA) {
        bool isA = id < NSPA;
        const float4* src = (const float4*)(isA ? A : Bn);
        size_t t8 = (size_t)(id - (isA ? 0 : NSPA)) * 256 + tid;   // 8-float unit
        float4 v0 = src[t8 * 2];
        float4 v1 = src[t8 * 2 + 1];
        size_t i = t8 * 8;
        size_t row = i / EMB + (isA ? 0 : (size_t)MROWS);
        size_t c = i % EMB;
        __half h[8], l[8];
        split_h(v0.x,h[0],l[0]); split_h(v0.y,h[1],l[1]);
        split_h(v0.z,h[2],l[2]); split_h(v0.w,h[3],l[3]);
        split_h(v1.x,h[4],l[4]); split_h(v1.y,h[5],l[5]);
        split_h(v1.z,h[6],l[6]); split_h(v1.w,h[7],l[7]);
        __half* dst = ABh + row * (2*EMB) + c;
        *(uint4*)dst        = *(uint4*)h;    // 8 hi halves = 16B
        *(uint4*)(dst+EMB)  = *(uint4*)l;    // 8 lo halves = 16B
        return;
    }
    id -= 2 * NSPA;
    int tx = tid & 31, ty = tid >> 5;
    bool isW1 = id < NW1;
    int id2 = isW1 ? id : id - NW1;
    int R = isW1 ? EMB : HID;
    const float* W = isW1 ? W1 : W2;
    __half* WT = isW1 ? W1Th : W2Th;
    int rt = R / 32;
    int r0 = (id2 % rt) * 32, c0 = (id2 / rt) * 32;
#pragma unroll
    for (int k = 0; k < 4; ++k)
        tile[k*8+ty][tx] = W[(size_t)(r0 + k*8 + ty) * HID + c0 + tx];
    __syncthreads();
#pragma unroll
    for (int k = 0; k < 4; ++k) {
        int c = c0 + k*8 + ty;
        float v = tile[tx][k*8+ty];
        __half h, l; split_h(v, h, l);
        WT[(size_t)c * (2*R) + r0 + tx]     = h;
        WT[(size_t)c * (2*R) + R + r0 + tx] = l;
    }
}

// ================= combine partials =================
__global__ void __launch_bounds__(256)
combine_kernel(const float* __restrict__ rpm, const float* __restrict__ rps,
               const float* __restrict__ cpm, const float* __restrict__ cps,
               float* __restrict__ rmax, float* __restrict__ rsum,
               float* __restrict__ cmax, float* __restrict__ csum)
{
    int g = blockIdx.x * 256 + threadIdx.x;
    const float *pm, *ps;
    float *om, *os;
    int id = g;
    if (g < MROWS) { pm = rpm; ps = rps; om = rmax; os = rsum; }
    else { id = g - MROWS; pm = cpm; ps = cps; om = cmax; os = csum; }
    float m = pm[id], s = ps[id];
#pragma unroll
    for (int k = 1; k < 8; ++k)
        sm_merge(m, s, pm[(size_t)k * MROWS + id], ps[(size_t)k * MROWS + id]);
    om[id] = m; os[id] = s;
}

// ================= normalize =================
__global__ void __launch_bounds__(256)
normexp_kernel(const float* __restrict__ E, __half* __restrict__ Pall,
               const float* __restrict__ rmax, const float* __restrict__ rsum,
               const float* __restrict__ cmax, const float* __restrict__ csum)
{
    __shared__ float tile[32][33];
    int b = blockIdx.z, a0 = blockIdx.y * 32, c0 = blockIdx.x * 32;
    int tx = threadIdx.x, ty = threadIdx.y;
    const float* Eb = E + (size_t)b * TT * TT;
    __half* P2b = Pall + (size_t)b * TT * TT;
    __half* Pb  = Pall + (size_t)(BSZ + b) * TT * TT;
#pragma unroll
    for (int k = 0; k < 4; ++k) {
        int a = a0 + k*8 + ty;
        float v = Eb[(size_t)a * TT + c0 + tx];
        tile[k*8+ty][tx] = v;
        int grr = b * TT + a;
        Pb[(size_t)a * TT + c0 + tx] =
            __float2half_rn(__expf(v - rmax[grr]) * __frcp_rn(rsum[grr]));
    }
    __syncthreads();
#pragma unroll
    for (int k = 0; k < 4; ++k) {
        int c = c0 + k*8 + ty;
        float v = tile[tx][k*8+ty];
        int gc = b * TT + c;
        P2b[(size_t)c * TT + a0 + tx] =
            __float2half_rn(__expf(v - cmax[gc]) * __frcp_rn(csum[gc]));
    }
}

// ================= launch =================
extern "C" void kernel_launch(void* const* d_in, const int* in_sizes, int n_in,
                              void* d_out, int out_size)
{
    const float* Ain = (const float*)d_in[0];
    const float* Bin = (const float*)d_in[1];
    const float* W1  = (const float*)d_in[2];
    const float* b1  = (const float*)d_in[3];
    const float* W2  = (const float*)d_in[4];
    const float* b2  = (const float*)d_in[5];
    float* outp = (float*)d_out;

    __half *ABh, *W1Th, *W2Th, *Hh, *Fh, *Pall;
    float *E, *rm, *rs, *cm, *cs, *rpm, *rps, *cpm, *cps;
    cudaGetSymbolAddress((void**)&ABh,  g_ABh);
    cudaGetSymbolAddress((void**)&W1Th, g_W1Th);
    cudaGetSymbolAddress((void**)&W2Th, g_W2Th);
    cudaGetSymbolAddress((void**)&Hh,   g_Hh);
    cudaGetSymbolAddress((void**)&Fh,   g_Fh);
    cudaGetSymbolAddress((void**)&E,    g_E);
    cudaGetSymbolAddress((void**)&Pall, g_Pall);
    cudaGetSymbolAddress((void**)&rm,   g_rmax);
    cudaGetSymbolAddress((void**)&rs,   g_rsum);
    cudaGetSymbolAddress((void**)&cm,   g_cmax);
    cudaGetSymbolAddress((void**)&cs,   g_csum);
    cudaGetSymbolAddress((void**)&rpm,  g_rpm);
    cudaGetSymbolAddress((void**)&rps,  g_rps);
    cudaGetSymbolAddress((void**)&cpm,  g_cpm);
    cudaGetSymbolAddress((void**)&cps,  g_cps);

    cudaFuncSetAttribute(gemm_h<true,  true,  true,  false, false>, cudaFuncAttributeMaxDynamicSharedMemorySize, SMEM3);
    cudaFuncSetAttribute(gemm_h<true,  false, false, false, true >, cudaFuncAttributeMaxDynamicSharedMemorySize, SMEM3);
    cudaFuncSetAttribute(gemm_h<false, false, false, true,  false>, cudaFuncAttributeMaxDynamicSharedMemorySize, SMEMP);

    // 1) prep
    prep_kernel<<<PREP_BLOCKS, 256>>>(Ain, Bin, W1, W2, ABh, W1Th, W2Th);

    // 2) MLP layer 1
    gemm_h<true, true, true, false, false><<<dim3(HID/BN, 2*MROWS/BM, 1), NTHR, SMEM3>>>(
        ABh, 2*EMB, 0, W1Th, 2*EMB, 0, b1, Hh, 2*HID, 0, HID, EMB, EMB,
        nullptr, nullptr, nullptr, nullptr);

    // 3) MLP layer 2
    gemm_h<true, true, true, false, false><<<dim3(HID/BN, 2*MROWS/BM, 1), NTHR, SMEM3>>>(
        Hh, 2*HID, 0, W2Th, 2*HID, 0, b2, Fh, 2*HID, 0, HID, HID, HID,
        nullptr, nullptr, nullptr, nullptr);

    // 4) e = f_A @ f_B^T with fused softmax partial stats
    gemm_h<true, false, false, false, true><<<dim3(TT/BN, TT/BM, BSZ), NTHR, SMEM3>>>(
        Fh, 2*HID, (unsigned long long)TT*2*HID,
        Fh + (size_t)MROWS*2*HID, 2*HID, (unsigned long long)TT*2*HID,
        nullptr, E, TT, (unsigned long long)TT*TT, TT, HID, HID,
        rpm, rps, cpm, cps);

    // 5) combine partials
    combine_kernel<<<2*MROWS/256, 256>>>(rpm, rps, cpm, cps, rm, rs, cm, cs);

    // 6) normalize -> Pall = [P2 | P]
    normexp_kernel<<<dim3(TT/32, TT/32, BSZ), dim3(32, 8)>>>(E, Pall, rm, rs, cm, cs);

    // 7) alpha (z 0..15: P2 @ A) + beta (z 16..31: P @ B)
    gemm_h<false, false, false, true, false><<<dim3(EMB/BN, TT/BM, 2*BSZ), NTHR, SMEMP>>>(
        Pall, TT, (unsigned long long)TT*TT,
        ABh, 2*EMB, (unsigned long long)TT*2*EMB,
        nullptr, outp, EMB, (unsigned long long)TT*EMB, EMB, TT, 0,
        nullptr, nullptr, nullptr, nullptr);
}

// round 17
// speedup vs baseline: 1.0521x; 1.0187x over previous
#include <cuda_runtime.h>
#include <cuda_fp16.h>
#include <cstdint>

#define BSZ 16
#define TT  1024
#define EMB 768
#define HID 1024
#define MROWS (BSZ*TT)

// ================= scratch =================
__device__ __align__(128) __half g_ABh [(size_t)2*MROWS*2*EMB];
__device__ __align__(128) __half g_W1Th[(size_t)HID*2*EMB];
__device__ __align__(128) __half g_W2Th[(size_t)HID*2*HID];
__device__ __align__(128) __half g_Hh  [(size_t)2*MROWS*2*HID];
__device__ __align__(128) __half g_Fh  [(size_t)2*MROWS*2*HID];
__device__ __align__(128) float  g_E   [(size_t)BSZ*TT*TT];
__device__ __align__(128) __half g_Pall[(size_t)2*BSZ*TT*TT];   // [P2 | P]
__device__ float g_rpm[8*MROWS], g_rps[8*MROWS];   // row partials (per n-block)
__device__ float g_cpm[8*MROWS], g_cps[8*MROWS];   // col partials (per m-block)

// ================= helpers =================
__device__ __forceinline__ uint32_t smem_u32(const void* p) {
    uint32_t a;
    asm("{ .reg .u64 t; cvta.to.shared.u64 t, %1; cvt.u32.u64 %0, t; }" : "=r"(a) : "l"(p));
    return a;
}
__device__ __forceinline__ void mma_f16(float* d, const uint32_t* a, const uint32_t* b) {
    asm volatile("mma.sync.aligned.m16n8k16.row.col.f32.f16.f16.f32 "
        "{%0,%1,%2,%3}, {%4,%5,%6,%7}, {%8,%9}, {%0,%1,%2,%3};"
        : "+f"(d[0]), "+f"(d[1]), "+f"(d[2]), "+f"(d[3])
        : "r"(a[0]), "r"(a[1]), "r"(a[2]), "r"(a[3]), "r"(b[0]), "r"(b[1]));
}
__device__ __forceinline__ void ldsm(uint32_t* r, uint32_t a) {
    asm volatile("ldmatrix.sync.aligned.m8n8.x4.shared.b16 {%0,%1,%2,%3}, [%4];"
        : "=r"(r[0]), "=r"(r[1]), "=r"(r[2]), "=r"(r[3]) : "r"(a));
}
__device__ __forceinline__ void ldsmT(uint32_t* r, uint32_t a) {
    asm volatile("ldmatrix.sync.aligned.m8n8.x4.trans.shared.b16 {%0,%1,%2,%3}, [%4];"
        : "=r"(r[0]), "=r"(r[1]), "=r"(r[2]), "=r"(r[3]) : "r"(a));
}
__device__ __forceinline__ void cp16(uint32_t d, const void* s) {
    asm volatile("cp.async.cg.shared.global [%0], [%1], 16;" :: "r"(d), "l"(s) : "memory");
}
__device__ __forceinline__ void split_h(float v, __half& hi, __half& lo) {
    hi = __float2half_rn(v);
    lo = __float2half_rn(v - __half2float(hi));
}
__device__ __forceinline__ void sm_merge(float& m, float& s, float om, float os) {
    float M = fmaxf(m, om);
    s = s * __expf(m - M) + os * __expf(om - M);
    m = M;
}

// ================= fp16 mma GEMM (fused 3-term split) =================
#define BM 128
#define BN 128
#define BKH 32
#define NTHR 256
#define SROW 80
#define SROWT 272
#define STG3 40960u
#define STGP 18944u
#define ALO_OFF 10240u
#define BHI_OFF 20480u
#define BLO_OFF 30720u
#define BT_OFF  10240u
#define SMEM3 (2*40960)
#define SMEMP3 (3*18944)

template<bool SPLIT3>
__device__ __forceinline__ void cp_stage32(uint32_t st,
    const __half* __restrict__ ga, int lda,
    const __half* __restrict__ gb, int ldb, int loK, int tid)
{
    if (SPLIT3) {
#pragma unroll
        for (int i = 0; i < 8; ++i) {
            int u = tid + i * NTHR;
            int mat = u >> 9;
            int r = (u >> 2) & 127;
            int c = u & 3;
            const __half* src = ((mat < 2) ? ga : gb)
                              + ((mat & 1) ? loK : 0)
                              + (size_t)r * ((mat < 2) ? lda : ldb) + c * 8;
            cp16(st + (uint32_t)((mat * 128 + r) * SROW + c * 16), src);
        }
    } else {
#pragma unroll
        for (int i = 0; i < 2; ++i) {
            int u = tid + i * NTHR, r = u >> 2, c = u & 3;
            cp16(st + (uint32_t)(r * SROW + c * 16), ga + (size_t)r * lda + c * 8);
        }
#pragma unroll
        for (int i = 0; i < 2; ++i) {
            int u = tid + i * NTHR, r = u >> 4, c = u & 15;
            cp16(st + BT_OFF + (uint32_t)(r * SROWT + c * 16), gb + (size_t)r * ldb + c * 8);
        }
    }
}

template<int STAGES, bool SPLIT3, bool BIASRELU, bool HALFSPLITOUT, bool SWAPOUT, bool STATS>
__global__ void __launch_bounds__(NTHR, 2)
gemm_h(const __half* __restrict__ Aop, int lda, unsigned long long sA,
       const __half* __restrict__ Bop, int ldb, unsigned long long sB,
       const float* __restrict__ bias,
       void* __restrict__ Cv, int ldc, unsigned long long sC,
       int N, int K, int loK,
       float* __restrict__ rpm, float* __restrict__ rps,
       float* __restrict__ cpm, float* __restrict__ cps)
{
    extern __shared__ __align__(128) __half smh[];
    uint32_t sbase = smem_u32(smh);
    constexpr uint32_t STG = SPLIT3 ? STG3 : STGP;
    const int tid = threadIdx.x, lane = tid & 31, wid = tid >> 5;
    const int wm = wid >> 2, wn = wid & 3, gr = lane >> 2, tc = lane & 3;
    const int m0 = blockIdx.y * BM, n0 = blockIdx.x * BN;
    const int z  = blockIdx.z;

    const __half* Abase = Aop + (size_t)z * sA + (size_t)m0 * lda;
    const __half* Bbase = SPLIT3
        ? (Bop + (size_t)z * sB + (size_t)n0 * ldb)
        : (Bop + (size_t)z * sB + n0);
    const int NT = K / BKH;

    const int lg = lane >> 3, r8 = lane & 7;
    uint32_t aOff[4], bOff[2];
#pragma unroll
    for (int mi = 0; mi < 4; ++mi)
        aOff[mi] = (uint32_t)((wm * 64 + mi * 16 + (lg & 1) * 8 + r8) * SROW
                              + (lg >> 1) * 16);
#pragma unroll
    for (int pn = 0; pn < 2; ++pn) {
        if (SPLIT3)
            bOff[pn] = (uint32_t)((wn * 32 + pn * 16 + (lg >> 1) * 8 + r8) * SROW
                                  + (lg & 1) * 16);
        else
            bOff[pn] = (uint32_t)(((lg & 1) * 8 + r8) * SROWT
                                  + (wn * 32 + pn * 16 + (lg >> 1) * 8) * 2);
    }

    float acc[4][4][4];
#pragma unroll
    for (int i = 0; i < 4; ++i)
#pragma unroll
        for (int j = 0; j < 4; ++j)
#pragma unroll
            for (int k = 0; k < 4; ++k) acc[i][j][k] = 0.f;

    auto stage_src = [&](int kt, const __half*& ga, const __half*& gb) {
        ga = Abase + kt * BKH;
        gb = SPLIT3 ? (Bbase + kt * BKH) : (Bbase + (size_t)kt * BKH * ldb);
    };

#pragma unroll
    for (int s = 0; s < STAGES - 1; ++s) {
        const __half *ga, *gb;
        stage_src(s, ga, gb);
        cp_stage32<SPLIT3>(sbase + (uint32_t)s * STG, ga, lda, gb, ldb, loK, tid);
        asm volatile("cp.async.commit_group;" ::: "memory");
    }

#pragma unroll 1
    for (int kt = 0; kt < NT; ++kt) {
        asm volatile("cp.async.wait_group %0;" :: "n"(STAGES - 2) : "memory");
        __syncthreads();
        if (kt + STAGES - 1 < NT) {
            const __half *ga, *gb;
            stage_src(kt + STAGES - 1, ga, gb);
            cp_stage32<SPLIT3>(sbase + (uint32_t)((kt + STAGES - 1) % STAGES) * STG,
                               ga, lda, gb, ldb, loK, tid);
        }
        asm volatile("cp.async.commit_group;" ::: "memory");

        uint32_t st = sbase + (uint32_t)(kt % STAGES) * STG;
#pragma unroll
        for (int ks = 0; ks < 2; ++ks) {
            if (SPLIT3) {
                const uint32_t kb = (uint32_t)(ks * 32);
                uint32_t bh[4][2], bl[4][2];
#pragma unroll
                for (int pn = 0; pn < 2; ++pn) {
                    uint32_t t[4];
                    ldsm(t, st + BHI_OFF + bOff[pn] + kb);
                    bh[2*pn][0]=t[0]; bh[2*pn][1]=t[1]; bh[2*pn+1][0]=t[2]; bh[2*pn+1][1]=t[3];
                    ldsm(t, st + BLO_OFF + bOff[pn] + kb);
                    bl[2*pn][0]=t[0]; bl[2*pn][1]=t[1]; bl[2*pn+1][0]=t[2]; bl[2*pn+1][1]=t[3];
                }
#pragma unroll
                for (int mi = 0; mi < 4; ++mi) {
                    uint32_t ah[4], al[4];
                    ldsm(ah, st + aOff[mi] + kb);
                    ldsm(al, st + ALO_OFF + aOff[mi] + kb);
#pragma unroll
                    for (int ni = 0; ni < 4; ++ni) mma_f16(acc[mi][ni], ah, bh[ni]);
#pragma unroll
                    for (int ni = 0; ni < 4; ++ni) mma_f16(acc[mi][ni], al, bh[ni]);
#pragma unroll
                    for (int ni = 0; ni < 4; ++ni) mma_f16(acc[mi][ni], ah, bl[ni]);
                }
            } else {
                const uint32_t kbA = (uint32_t)(ks * 32);
                const uint32_t kbB = (uint32_t)(ks * 16 * SROWT);
                uint32_t bf[4][2];
#pragma unroll
                for (int pn = 0; pn < 2; ++pn) {
                    uint32_t t[4];
                    ldsmT(t, st + BT_OFF + bOff[pn] + kbB);
                    bf[2*pn][0]=t[0]; bf[2*pn][1]=t[1]; bf[2*pn+1][0]=t[2]; bf[2*pn+1][1]=t[3];
                }
#pragma unroll
                for (int mi = 0; mi < 4; ++mi) {
                    uint32_t af[4];
                    ldsm(af, st + aOff[mi] + kbA);
#pragma unroll
                    for (int ni = 0; ni < 4; ++ni) mma_f16(acc[mi][ni], af, bf[ni]);
                }
            }
        }
    }

    // ---- store ----
    int ob = SWAPOUT ? ((z < BSZ) ? (BSZ + z) : (z - BSZ)) : z;
#pragma unroll
    for (int ni = 0; ni < 4; ++ni) {
        int col = n0 + wn * 32 + ni * 8 + 2 * tc;
        float b0 = 0.f, b1 = 0.f;
        if (BIASRELU) { b0 = __ldg(bias + col); b1 = __ldg(bias + col + 1); }
#pragma unroll
        for (int mi = 0; mi < 4; ++mi) {
            int row0 = m0 + wm * 64 + mi * 16 + gr;
            float v00 = acc[mi][ni][0], v01 = acc[mi][ni][1];
            float v10 = acc[mi][ni][2], v11 = acc[mi][ni][3];
            if (BIASRELU) {
                v00 = fmaxf(v00 + b0, 0.f); v01 = fmaxf(v01 + b1, 0.f);
                v10 = fmaxf(v10 + b0, 0.f); v11 = fmaxf(v11 + b1, 0.f);
                acc[mi][ni][0]=v00; acc[mi][ni][1]=v01; acc[mi][ni][2]=v10; acc[mi][ni][3]=v11;
            }
            if (HALFSPLITOUT) {
                __half* C = (__half*)Cv + (size_t)ob * sC;
                __half h00,l00,h01,l01,h10,l10,h11,l11;
                split_h(v00,h00,l00); split_h(v01,h01,l01);
                split_h(v10,h10,l10); split_h(v11,h11,l11);
                __half* p0 = C + (size_t)row0 * ldc + col;
                __half* p1 = C + (size_t)(row0 + 8) * ldc + col;
                *(__half2*)p0       = __halves2half2(h00, h01);
                *(__half2*)(p0 + N) = __halves2half2(l00, l01);
                *(__half2*)p1       = __halves2half2(h10, h11);
                *(__half2*)(p1 + N) = __halves2half2(l10, l11);
            } else {
                float* C = (float*)Cv + (size_t)ob * sC;
                *(float2*)(C + (size_t)row0 * ldc + col)       = make_float2(v00, v01);
                *(float2*)(C + (size_t)(row0 + 8) * ldc + col) = make_float2(v10, v11);
            }
        }
    }

    // ---- fused softmax partial stats (e-GEMM only) ----
    if (STATS) {
        __syncthreads();
        float2* smR = (float2*)smh;            // [128][4]
        float2* smC = ((float2*)smh) + 512;    // [128][2]
#pragma unroll
        for (int mi = 0; mi < 4; ++mi)
#pragma unroll
            for (int h = 0; h < 2; ++h) {
                float m = -1e30f;
#pragma unroll
                for (int ni = 0; ni < 4; ++ni)
                    m = fmaxf(m, fmaxf(acc[mi][ni][2*h], acc[mi][ni][2*h+1]));
                float s = 0.f;
#pragma unroll
                for (int ni = 0; ni < 4; ++ni)
                    s += __expf(acc[mi][ni][2*h] - m) + __expf(acc[mi][ni][2*h+1] - m);
#pragma unroll
                for (int o = 1; o <= 2; o <<= 1)
                    sm_merge(m, s, __shfl_xor_sync(~0u, m, o), __shfl_xor_sync(~0u, s, o));
                if (tc == 0)
                    smR[(wm*64 + mi*16 + h*8 + gr) * 4 + wn] = make_float2(m, s);
            }
#pragma unroll
        for (int ni = 0; ni < 4; ++ni)
#pragma unroll
            for (int j = 0; j < 2; ++j) {
                float m = -1e30f;
#pragma unroll
                for (int mi = 0; mi < 4; ++mi)
                    m = fmaxf(m, fmaxf(acc[mi][ni][j], acc[mi][ni][j+2]));
                float s = 0.f;
#pragma unroll
                for (int mi = 0; mi < 4; ++mi)
                    s += __expf(acc[mi][ni][j] - m) + __expf(acc[mi][ni][j+2] - m);
#pragma unroll
                for (int o = 4; o <= 16; o <<= 1)
                    sm_merge(m, s, __shfl_xor_sync(~0u, m, o), __shfl_xor_sync(~0u, s, o));
                if (gr == 0)
                    smC[(wn*32 + ni*8 + 2*tc + j) * 2 + wm] = make_float2(m, s);
            }
        __syncthreads();
        if (tid < 128) {
            float2 p = smR[tid * 4];
            float m = p.x, s = p.y;
#pragma unroll
            for (int w = 1; w < 4; ++w) {
                float2 q = smR[tid * 4 + w];
                sm_merge(m, s, q.x, q.y);
            }
            size_t idx = (size_t)blockIdx.x * MROWS + (size_t)z * TT + m0 + tid;
            rpm[idx] = m; rps[idx] = s;
        } else {
            int cl = tid - 128;
            float2 p = smC[cl * 2];
            float m = p.x, s = p.y;
            float2 q = smC[cl * 2 + 1];
            sm_merge(m, s, q.x, q.y);
            size_t idx = (size_t)blockIdx.y * MROWS + (size_t)z * TT + n0 + cl;
            cpm[idx] = m; cps[idx] = s;
        }
    }
}

// ================= prep (wide stores: 8 floats/thread) =================
#define NSPA ((MROWS*EMB)/2048)
#define NW1  ((EMB/32)*(HID/32))
#define NW2  ((HID/32)*(HID/32))
#define PREP_BLOCKS (2*NSPA + NW1 + NW2)

__global__ void __launch_bounds__(256)
prep_kernel(const float* __restrict__ A, const float* __restrict__ Bn,
            const float* __restrict__ W1, const float* __restrict__ W2,
            __half* __restrict__ ABh, __half* __restrict__ W1Th,
            __half* __restrict__ W2Th)
{
    __shared__ float tile[32][33];
    int id = blockIdx.x, tid = threadIdx.x;
    if (id < 2 * NSPA) {
        bool isA = id < NSPA;
        const float4* src = (const float4*)(isA ? A : Bn);
        size_t t8 = (size_t)(id - (isA ? 0 : NSPA)) * 256 + tid;
        float4 v0 = src[t8 * 2];
        float4 v1 = src[t8 * 2 + 1];
        size_t i = t8 * 8;
        size_t row = i / EMB + (isA ? 0 : (size_t)MROWS);
        size_t c = i % EMB;
        __half h[8], l[8];
        split_h(v0.x,h[0],l[0]); split_h(v0.y,h[1],l[1]);
        split_h(v0.z,h[2],l[2]); split_h(v0.w,h[3],l[3]);
        split_h(v1.x,h[4],l[4]); split_h(v1.y,h[5],l[5]);
        split_h(v1.z,h[6],l[6]); split_h(v1.w,h[7],l[7]);
        __half* dst = ABh + row * (2*EMB) + c;
        *(uint4*)dst        = *(uint4*)h;
        *(uint4*)(dst+EMB)  = *(uint4*)l;
        return;
    }
    id -= 2 * NSPA;
    int tx = tid & 31, ty = tid >> 5;
    bool isW1 = id < NW1;
    int id2 = isW1 ? id : id - NW1;
    int R = isW1 ? EMB : HID;
    const float* W = isW1 ? W1 : W2;
    __half* WT = isW1 ? W1Th : W2Th;
    int rt = R / 32;
    int r0 = (id2 % rt) * 32, c0 = (id2 / rt) * 32;
#pragma unroll
    for (int k = 0; k < 4; ++k)
        tile[k*8+ty][tx] = W[(size_t)(r0 + k*8 + ty) * HID + c0 + tx];
    __syncthreads();
#pragma unroll
    for (int k = 0; k < 4; ++k) {
        int c = c0 + k*8 + ty;
        float v = tile[tx][k*8+ty];
        __half h, l; split_h(v, h, l);
        WT[(size_t)c * (2*R) + r0 + tx]     = h;
        WT[(size_t)c * (2*R) + R + r0 + tx] = l;
    }
}

// ================= normalize (with inline partial combine) =================
__global__ void __launch_bounds__(256)
normexp_kernel(const float* __restrict__ E, __half* __restrict__ Pall,
               const float* __restrict__ rpm, const float* __restrict__ rps,
               const float* __restrict__ cpm, const float* __restrict__ cps)
{
    __shared__ float tile[32][33];
    __shared__ float2 rowMS[32], colMS[32];
    int b = blockIdx.z, a0 = blockIdx.y * 32, c0 = blockIdx.x * 32;
    int tx = threadIdx.x, ty = threadIdx.y;
    int t = ty * 32 + tx;
    if (t < 32) {                // combine 8 row partials for row a0+t
        size_t base = (size_t)b * TT + a0 + t;
        float m = rpm[base], s = rps[base];
#pragma unroll
        for (int k = 1; k < 8; ++k)
            sm_merge(m, s, rpm[(size_t)k * MROWS + base], rps[(size_t)k * MROWS + base]);
        rowMS[t] = make_float2(m, __frcp_rn(s));
    } else if (t < 64) {         // combine 8 col partials for col c0+(t-32)
        size_t base = (size_t)b * TT + c0 + (t - 32);
        float m = cpm[base], s = cps[base];
#pragma unroll
        for (int k = 1; k < 8; ++k)
            sm_merge(m, s, cpm[(size_t)k * MROWS + base], cps[(size_t)k * MROWS + base]);
        colMS[t - 32] = make_float2(m, __frcp_rn(s));
    }
    __syncthreads();

    const float* Eb = E + (size_t)b * TT * TT;
    __half* P2b = Pall + (size_t)b * TT * TT;
    __half* Pb  = Pall + (size_t)(BSZ + b) * TT * TT;
#pragma unroll
    for (int k = 0; k < 4; ++k) {
        int a = a0 + k*8 + ty;
        float v = Eb[(size_t)a * TT + c0 + tx];
        tile[k*8+ty][tx] = v;
        float2 rs = rowMS[k*8 + ty];
        Pb[(size_t)a * TT + c0 + tx] = __float2half_rn(__expf(v - rs.x) * rs.y);
    }
    __syncthreads();
#pragma unroll
    for (int k = 0; k < 4; ++k) {
        int c = c0 + k*8 + ty;
        float v = tile[tx][k*8+ty];
        float2 cs = colMS[k*8 + ty];
        P2b[(size_t)c * TT + a0 + tx] = __float2half_rn(__expf(v - cs.x) * cs.y);
    }
}

// ================= launch =================
extern "C" void kernel_launch(void* const* d_in, const int* in_sizes, int n_in,
                              void* d_out, int out_size)
{
    const float* Ain = (const float*)d_in[0];
    const float* Bin = (const float*)d_in[1];
    const float* W1  = (const float*)d_in[2];
    const float* b1  = (const float*)d_in[3];
    const float* W2  = (const float*)d_in[4];
    const float* b2  = (const float*)d_in[5];
    float* outp = (float*)d_out;

    __half *ABh, *W1Th, *W2Th, *Hh, *Fh, *Pall;
    float *E, *rpm, *rps, *cpm, *cps;
    cudaGetSymbolAddress((void**)&ABh,  g_ABh);
    cudaGetSymbolAddress((void**)&W1Th, g_W1Th);
    cudaGetSymbolAddress((void**)&W2Th, g_W2Th);
    cudaGetSymbolAddress((void**)&Hh,   g_Hh);
    cudaGetSymbolAddress((void**)&Fh,   g_Fh);
    cudaGetSymbolAddress((void**)&E,    g_E);
    cudaGetSymbolAddress((void**)&Pall, g_Pall);
    cudaGetSymbolAddress((void**)&rpm,  g_rpm);
    cudaGetSymbolAddress((void**)&rps,  g_rps);
    cudaGetSymbolAddress((void**)&cpm,  g_cpm);
    cudaGetSymbolAddress((void**)&cps,  g_cps);

    cudaFuncSetAttribute(gemm_h<2, true,  true,  true,  false, false>, cudaFuncAttributeMaxDynamicSharedMemorySize, SMEM3);
    cudaFuncSetAttribute(gemm_h<2, true,  false, false, false, true >, cudaFuncAttributeMaxDynamicSharedMemorySize, SMEM3);
    cudaFuncSetAttribute(gemm_h<3, false, false, false, true,  false>, cudaFuncAttributeMaxDynamicSharedMemorySize, SMEMP3);

    // 1) prep
    prep_kernel<<<PREP_BLOCKS, 256>>>(Ain, Bin, W1, W2, ABh, W1Th, W2Th);

    // 2) MLP layer 1
    gemm_h<2, true, true, true, false, false><<<dim3(HID/BN, 2*MROWS/BM, 1), NTHR, SMEM3>>>(
        ABh, 2*EMB, 0, W1Th, 2*EMB, 0, b1, Hh, 2*HID, 0, HID, EMB, EMB,
        nullptr, nullptr, nullptr, nullptr);

    // 3) MLP layer 2
    gemm_h<2, true, true, true, false, false><<<dim3(HID/BN, 2*MROWS/BM, 1), NTHR, SMEM3>>>(
        Hh, 2*HID, 0, W2Th, 2*HID, 0, b2, Fh, 2*HID, 0, HID, HID, HID,
        nullptr, nullptr, nullptr, nullptr);

    // 4) e = f_A @ f_B^T with fused softmax partial stats
    gemm_h<2, true, false, false, false, true><<<dim3(TT/BN, TT/BM, BSZ), NTHR, SMEM3>>>(
        Fh, 2*HID, (unsigned long long)TT*2*HID,
        Fh + (size_t)MROWS*2*HID, 2*HID, (unsigned long long)TT*2*HID,
        nullptr, E, TT, (unsigned long long)TT*TT, TT, HID, HID,
        rpm, rps, cpm, cps);

    // 5) normalize (combines partials inline) -> Pall = [P2 | P]
    normexp_kernel<<<dim3(TT/32, TT/32, BSZ), dim3(32, 8)>>>(E, Pall, rpm, rps, cpm, cps);

    // 6) alpha (z 0..15: P2 @ A) + beta (z 16..31: P @ B), 3-stage pipeline
    gemm_h<3, false, false, false, true, false><<<dim3(EMB/BN, TT/BM, 2*BSZ), NTHR, SMEMP3>>>(
        Pall, TT, (unsigned long long)TT*TT,
        ABh, 2*EMB, (unsigned long long)TT*2*EMB,
        nullptr, outp, EMB, (unsigned long long)TT*EMB, EMB, TT, 0,
        nullptr, nullptr, nullptr, nullptr);
}